// round 9
// baseline (speedup 1.0000x reference)
#include <cuda_runtime.h>
#include <math.h>

#define S_LEN 4096
#define D_MODEL 1024
#define NH 16
#define HD 64

// Scratch (__device__ globals: allocation-free)
__device__ float g_qkv[(size_t)S_LEN * 3 * D_MODEL];     // [S][3D] (q,k tf32; v region unused)
__device__ float g_v[(size_t)D_MODEL * S_LEN];           // [dv][S] transposed V, tf32
__device__ float g_ctx[(size_t)S_LEN * D_MODEL];         // [S][D] tf32
__device__ float g_xc[(size_t)S_LEN * D_MODEL];          // x, tf32
__device__ float g_wqkvT[(size_t)3 * D_MODEL * D_MODEL]; // [3D][D] tf32
__device__ float g_wprojT[(size_t)D_MODEL * D_MODEL];    // [D][D] tf32

// ---------------------------------------------------------------------------
// helpers
// ---------------------------------------------------------------------------
__device__ __forceinline__ unsigned f2tf(float f) {
    unsigned u;
    asm("cvt.rna.tf32.f32 %0, %1;" : "=r"(u) : "f"(f));
    return u;
}
__device__ __forceinline__ float tf32r(float f) { return __uint_as_float(f2tf(f)); }

__device__ __forceinline__ void mma8(float* d, const unsigned* a, const unsigned* b) {
    asm volatile("mma.sync.aligned.m16n8k8.row.col.f32.tf32.tf32.f32 "
        "{%0,%1,%2,%3}, {%4,%5,%6,%7}, {%8,%9}, {%0,%1,%2,%3};"
        : "+f"(d[0]), "+f"(d[1]), "+f"(d[2]), "+f"(d[3])
        : "r"(a[0]), "r"(a[1]), "r"(a[2]), "r"(a[3]), "r"(b[0]), "r"(b[1]));
}
__device__ __forceinline__ void ldsm4(unsigned* r, unsigned addr) {
    asm volatile("ldmatrix.sync.aligned.m8n8.x4.shared.b16 {%0,%1,%2,%3}, [%4];"
        : "=r"(r[0]), "=r"(r[1]), "=r"(r[2]), "=r"(r[3]) : "r"(addr));
}
#define CP16(dst, src) asm volatile("cp.async.cg.shared.global [%0], [%1], 16;" :: "r"(dst), "l"(src))
#define CP_COMMIT()    asm volatile("cp.async.commit_group;" ::: "memory")
#define CP_WAIT1()     asm volatile("cp.async.wait_group 1;" ::: "memory")

// ---------------------------------------------------------------------------
// One-time converters
// ---------------------------------------------------------------------------
__global__ void conv_tf32_kernel(const float4* __restrict__ src, float4* __restrict__ dst, int n4) {
    int i = blockIdx.x * blockDim.x + threadIdx.x;
    if (i < n4) {
        float4 v = src[i];
        dst[i] = make_float4(tf32r(v.x), tf32r(v.y), tf32r(v.z), tf32r(v.w));
    }
}
// src [R][C] -> dst [C][R], tf32-rounded
__global__ void convT_tf32_kernel(const float* __restrict__ src, float* __restrict__ dst, int R, int C) {
    __shared__ float tile[32][33];
    int c0 = blockIdx.x * 32, r0 = blockIdx.y * 32;
    int tx = threadIdx.x, ty = threadIdx.y;
    #pragma unroll
    for (int j = 0; j < 32; j += 8)
        tile[ty + j][tx] = src[(size_t)(r0 + ty + j) * C + c0 + tx];
    __syncthreads();
    #pragma unroll
    for (int j = 0; j < 32; j += 8)
        dst[(size_t)(c0 + ty + j) * R + r0 + tx] = tf32r(tile[tx][ty + j]);
}

// ---------------------------------------------------------------------------
// GEMM: C[M,N] = A[M,K] @ BT[N,K]^T + bias. A/BT pre-tf32. 3-stage cp.async.
// 128x128 block, BK=32, 8 warps (4x2), warp 32x64, all fragments via ldmatrix.
// Blocks with n0 >= vcol0 write transposed (f2tf) to VT[n-vcol0][M] instead.
// ---------------------------------------------------------------------------
#define GSTR 36          // words/row (144B), 36%8==4 -> LDSM conflict-free
#define G_STAGE 36864    // bytes/stage: (128*36 + 128*36)*4
#define G_BOFF 18432     // byte offset of B tile in stage

__global__ __launch_bounds__(256, 2) void gemm_tc_kernel(
    const float* __restrict__ A, const float* __restrict__ BT,
    const float* __restrict__ bias, float* __restrict__ C,
    int M, int N, int K, float* __restrict__ VT, int vcol0, int cvt_out)
{
    extern __shared__ float gsm[];
    const unsigned sb = (unsigned)__cvta_generic_to_shared(gsm);

    const int tid = threadIdx.x;
    const int warp = tid >> 5, lane = tid & 31;
    const int g = lane >> 2, t = lane & 3;
    const int wm = (warp & 3) * 32;
    const int wn = (warp >> 2) * 64;
    const int m0 = blockIdx.y * 128, n0 = blockIdx.x * 128;

    // loader slots (row = tid>>1, 4 chunks of 16B at half (tid&1))
    const int lrow = tid >> 1;
    const float* aSrc = A + (size_t)(m0 + lrow) * K + (tid & 1) * 16;
    const float* bSrc = BT + (size_t)(n0 + lrow) * K + (tid & 1) * 16;
    const unsigned aDst = sb + lrow * 144 + (tid & 1) * 64;
    const unsigned bDst = sb + G_BOFF + lrow * 144 + (tid & 1) * 64;

    // ldmatrix lane offsets
    const int r8  = (lane & 7) + ((lane >> 3) & 1) * 8;
    const int c4  = (lane >> 4) * 4;
    const int r8v = (lane >> 4) * 8 + (lane & 7);
    const int c4v = ((lane >> 3) & 1) * 4;
    const unsigned aFrag = sb + (wm + r8) * 144 + c4 * 4;
    const unsigned bFrag = sb + G_BOFF + (wn + r8v) * 144 + c4v * 4;

    float acc[2][8][4];
    #pragma unroll
    for (int mt = 0; mt < 2; ++mt)
        #pragma unroll
        for (int nt = 0; nt < 8; ++nt)
            #pragma unroll
            for (int i = 0; i < 4; ++i) acc[mt][nt][i] = 0.f;

    const int KT = K / 32;

    // prologue: stages 0,1
    #pragma unroll
    for (int s = 0; s < 2; ++s) {
        #pragma unroll
        for (int j = 0; j < 4; ++j) {
            CP16(aDst + s * G_STAGE + j * 16, aSrc + s * 32 + j * 4);
            CP16(bDst + s * G_STAGE + j * 16, bSrc + s * 32 + j * 4);
        }
        CP_COMMIT();
    }

    for (int kt = 0; kt < KT; ++kt) {
        CP_WAIT1();
        __syncthreads();

        if (kt + 2 < KT) {
            int st = (kt + 2) % 3;
            #pragma unroll
            for (int j = 0; j < 4; ++j) {
                CP16(aDst + st * G_STAGE + j * 16, aSrc + (kt + 2) * 32 + j * 4);
                CP16(bDst + st * G_STAGE + j * 16, bSrc + (kt + 2) * 32 + j * 4);
            }
        }
        CP_COMMIT();

        const unsigned stb = (kt % 3) * G_STAGE;
        #pragma unroll
        for (int c = 0; c < 4; ++c) {
            unsigned a0[4], a1[4];
            ldsm4(a0, aFrag + stb + c * 32);
            ldsm4(a1, aFrag + stb + 2304 + c * 32);   // +16 rows
            #pragma unroll
            for (int p = 0; p < 4; ++p) {
                unsigned b[4];
                ldsm4(b, bFrag + stb + p * 2304 + c * 32);
                mma8(acc[0][2 * p],     a0, b);
                mma8(acc[0][2 * p + 1], a0, b + 2);
                mma8(acc[1][2 * p],     a1, b);
                mma8(acc[1][2 * p + 1], a1, b + 2);
            }
        }
    }

    if (!VT || n0 < vcol0) {
        #pragma unroll
        for (int mt = 0; mt < 2; ++mt) {
            int row = m0 + wm + mt * 16 + g;
            #pragma unroll
            for (int nt = 0; nt < 8; ++nt) {
                int col = n0 + wn + nt * 8 + 2 * t;
                float b0 = bias[col], b1 = bias[col + 1];
                float v0 = acc[mt][nt][0] + b0, v1 = acc[mt][nt][1] + b1;
                float v2 = acc[mt][nt][2] + b0, v3 = acc[mt][nt][3] + b1;
                if (cvt_out) { v0 = tf32r(v0); v1 = tf32r(v1); v2 = tf32r(v2); v3 = tf32r(v3); }
                *(float2*)(C + (size_t)row * N + col)       = make_float2(v0, v1);
                *(float2*)(C + (size_t)(row + 8) * N + col) = make_float2(v2, v3);
            }
        }
    } else {
        // V block: smem transpose then coalesced rows of VT[dv][M]
        __syncthreads();
        #pragma unroll
        for (int mt = 0; mt < 2; ++mt) {
            int row = wm + mt * 16 + g;
            #pragma unroll
            for (int nt = 0; nt < 8; ++nt) {
                int col = wn + nt * 8 + 2 * t;
                float b0 = bias[n0 + col], b1 = bias[n0 + col + 1];
                gsm[row * 129 + col]           = tf32r(acc[mt][nt][0] + b0);
                gsm[row * 129 + col + 1]       = tf32r(acc[mt][nt][1] + b1);
                gsm[(row + 8) * 129 + col]     = tf32r(acc[mt][nt][2] + b0);
                gsm[(row + 8) * 129 + col + 1] = tf32r(acc[mt][nt][3] + b1);
            }
        }
        __syncthreads();
        #pragma unroll
        for (int j = 0; j < 16; ++j) {
            int d = warp + 8 * j;
            float4 o4;
            o4.x = gsm[(lane * 4 + 0) * 129 + d];
            o4.y = gsm[(lane * 4 + 1) * 129 + d];
            o4.z = gsm[(lane * 4 + 2) * 129 + d];
            o4.w = gsm[(lane * 4 + 3) * 129 + d];
            *(float4*)(VT + (size_t)(n0 - vcol0 + d) * M + m0 + lane * 4) = o4;
        }
    }
}

// ---------------------------------------------------------------------------
// Flash attention. qkv pre-tf32 ([S][3D] rows for Q,K), V from g_v[dv][S].
// Block = (head, 128-query tile), 8 warps x 16 rows. 2-stage cp.async K/V.
// All mma fragments via ldmatrix; P via quad shuffles.
// ---------------------------------------------------------------------------
#define AT_Q 34816      // Q bytes: 128*68*4
#define AT_T 17408      // K or V tile bytes: 64*68*4

__global__ __launch_bounds__(256, 2) void attn_tc_kernel(
    const float* __restrict__ qkv, const float* __restrict__ Vg,
    float* __restrict__ ctx)
{
    extern __shared__ float smf[];
    const unsigned sb = (unsigned)__cvta_generic_to_shared(smf);
    const unsigned qS = sb;
    const unsigned kS = sb + AT_Q;
    const unsigned vS = sb + AT_Q + 2 * AT_T;

    const int h  = blockIdx.y;
    const int qt = (int)gridDim.x - 1 - (int)blockIdx.x;
    const int q0 = qt * 128;
    const int tid = threadIdx.x;
    const int warp = tid >> 5, lane = tid & 31;
    const int g = lane >> 2, t = lane & 3;
    const int wm = warp * 16;

    // loader slots: row = tid>>2, 4 chunks of 16B at quarter (tid&3)
    const int lrow = tid >> 2, lq = tid & 3;
    const float* kSrc = qkv + (size_t)lrow * (3 * D_MODEL) + D_MODEL + h * HD + lq * 16;
    const float* vSrc = Vg + (size_t)(h * HD + lrow) * S_LEN + lq * 16;
    const unsigned kDst = kS + lrow * 272 + lq * 64;
    const unsigned vDst = vS + lrow * 272 + lq * 64;

    // ldmatrix lane offsets
    const int r8  = (lane & 7) + ((lane >> 3) & 1) * 8;
    const int c4  = (lane >> 4) * 4;
    const int r8v = (lane >> 4) * 8 + (lane & 7);
    const int c4v = ((lane >> 3) & 1) * 4;
    const unsigned qFrag = qS + (wm + r8) * 272 + c4 * 4;
    const unsigned kFrag = kS + r8v * 272 + c4v * 4;
    const unsigned vFrag = vS + r8v * 272 + c4v * 4;

    // Load Q (tf32 bits, exact *0.125 scale)
    const float* qb = qkv + (size_t)q0 * (3 * D_MODEL) + h * HD;
    for (int idx = tid; idx < 128 * 16; idx += 256) {
        int row = idx >> 4, dq = (idx & 15) << 2;
        float4 v = *(const float4*)(qb + (size_t)row * (3 * D_MODEL) + dq);
        *(float4*)(smf + row * 68 + dq) =
            make_float4(v.x * 0.125f, v.y * 0.125f, v.z * 0.125f, v.w * 0.125f);
    }

    float m_[2] = {-1e30f, -1e30f};
    float l_[2] = {0.f, 0.f};
    float o[8][4];
    #pragma unroll
    for (int nt = 0; nt < 8; ++nt)
        #pragma unroll
        for (int i = 0; i < 4; ++i) o[nt][i] = 0.f;

    const int nkt = 2 * qt + 2;
    const int src0 = (lane & ~3) | (t >> 1);
    const bool odd = (t & 1);

    // prologue: tiles 0,1
    #pragma unroll
    for (int s = 0; s < 2; ++s) {
        #pragma unroll
        for (int j = 0; j < 4; ++j) {
            CP16(kDst + s * AT_T + j * 16, kSrc + (size_t)s * 64 * (3 * D_MODEL) + j * 4);
            CP16(vDst + s * AT_T + j * 16, vSrc + s * 64 + j * 4);
        }
        CP_COMMIT();
    }

    for (int kt = 0; kt < nkt; ++kt) {
        CP_WAIT1();
        __syncthreads();

        const bool active = (kt * 64 <= q0 + wm + 15);
        const unsigned kb = kS + (kt & 1) * AT_T - kS + kFrag;   // kFrag + buf offset
        const unsigned kbuf = kFrag + (kt & 1) * AT_T;
        const unsigned vbuf = vFrag + (kt & 1) * AT_T;
        (void)kb;

        float s[8][4];
        if (active) {
            #pragma unroll
            for (int nt = 0; nt < 8; ++nt)
                #pragma unroll
                for (int i = 0; i < 4; ++i) s[nt][i] = 0.f;

            // S = Q K^T
            #pragma unroll
            for (int ks = 0; ks < 8; ++ks) {
                unsigned a[4];
                ldsm4(a, qFrag + ks * 32);
                #pragma unroll
                for (int p = 0; p < 4; ++p) {
                    unsigned b[4];
                    ldsm4(b, kbuf + p * 4352 + ks * 32);
                    mma8(s[2 * p],     a, b);
                    mma8(s[2 * p + 1], a, b + 2);
                }
            }

            // causal mask (diagonal tiles only)
            if (kt >= 2 * qt) {
                int r0 = q0 + wm + g;
                #pragma unroll
                for (int nt = 0; nt < 8; ++nt) {
                    int col = kt * 64 + nt * 8 + 2 * t;
                    if (col     > r0)     s[nt][0] = -1e30f;
                    if (col + 1 > r0)     s[nt][1] = -1e30f;
                    if (col     > r0 + 8) s[nt][2] = -1e30f;
                    if (col + 1 > r0 + 8) s[nt][3] = -1e30f;
                }
            }

            // online softmax
            #pragma unroll
            for (int r = 0; r < 2; ++r) {
                float tm = -1e30f;
                #pragma unroll
                for (int nt = 0; nt < 8; ++nt)
                    tm = fmaxf(tm, fmaxf(s[nt][2 * r], s[nt][2 * r + 1]));
                tm = fmaxf(tm, __shfl_xor_sync(0xffffffffu, tm, 1));
                tm = fmaxf(tm, __shfl_xor_sync(0xffffffffu, tm, 2));
                float mn = fmaxf(m_[r], tm);
                float rs = 0.f;
                #pragma unroll
                for (int nt = 0; nt < 8; ++nt) {
                    float p0 = __expf(s[nt][2 * r] - mn);
                    float p1 = __expf(s[nt][2 * r + 1] - mn);
                    s[nt][2 * r] = p0; s[nt][2 * r + 1] = p1;
                    rs += p0 + p1;
                }
                rs += __shfl_xor_sync(0xffffffffu, rs, 1);
                rs += __shfl_xor_sync(0xffffffffu, rs, 2);
                float alpha = __expf(m_[r] - mn);
                l_[r] = l_[r] * alpha + rs;
                #pragma unroll
                for (int nt = 0; nt < 8; ++nt) {
                    o[nt][2 * r] *= alpha; o[nt][2 * r + 1] *= alpha;
                }
                m_[r] = mn;
            }

            // O += P V (P gathered via quad shuffles, V via ldmatrix)
            #pragma unroll
            for (int ks = 0; ks < 8; ++ks) {
                float x0 = __shfl_sync(0xffffffffu, s[ks][0], src0);
                float x1 = __shfl_sync(0xffffffffu, s[ks][1], src0);
                float y0 = __shfl_sync(0xffffffffu, s[ks][2], src0);
                float y1 = __shfl_sync(0xffffffffu, s[ks][3], src0);
                float x2 = __shfl_sync(0xffffffffu, s[ks][0], src0 + 2);
                float x3 = __shfl_sync(0xffffffffu, s[ks][1], src0 + 2);
                float y2 = __shfl_sync(0xffffffffu, s[ks][2], src0 + 2);
                float y3 = __shfl_sync(0xffffffffu, s[ks][3], src0 + 2);
                unsigned a[4];
                a[0] = f2tf(odd ? x1 : x0);
                a[1] = f2tf(odd ? y1 : y0);
                a[2] = f2tf(odd ? x3 : x2);
                a[3] = f2tf(odd ? y3 : y2);
                #pragma unroll
                for (int p = 0; p < 4; ++p) {
                    unsigned b[4];
                    ldsm4(b, vbuf + p * 4352 + ks * 32);
                    mma8(o[2 * p],     a, b);
                    mma8(o[2 * p + 1], a, b + 2);
                }
            }
        }

        __syncthreads();
        if (kt + 2 < nkt) {
            int buf = kt & 1;
            #pragma unroll
            for (int j = 0; j < 4; ++j) {
                CP16(kDst + buf * AT_T + j * 16,
                     kSrc + (size_t)(kt + 2) * 64 * (3 * D_MODEL) + j * 4);
                CP16(vDst + buf * AT_T + j * 16, vSrc + (kt + 2) * 64 + j * 4);
            }
        }
        CP_COMMIT();
    }

    // epilogue: normalize, tf32-round (proj GEMM consumes), write ctx[q][h*64+d]
    float inv0 = 1.f / l_[0], inv1 = 1.f / l_[1];
    float* ob = ctx + (size_t)(q0 + wm) * D_MODEL + h * HD;
    #pragma unroll
    for (int nt = 0; nt < 8; ++nt) {
        int col = nt * 8 + 2 * t;
        *(float2*)(ob + (size_t)g * D_MODEL + col) =
            make_float2(tf32r(o[nt][0] * inv0), tf32r(o[nt][1] * inv0));
        *(float2*)(ob + (size_t)(g + 8) * D_MODEL + col) =
            make_float2(tf32r(o[nt][2] * inv1), tf32r(o[nt][3] * inv1));
    }
}

// ---------------------------------------------------------------------------
// Launch
// ---------------------------------------------------------------------------
extern "C" void kernel_launch(void* const* d_in, const int* in_sizes, int n_in,
                              void* d_out, int out_size)
{
    const float* x      = (const float*)d_in[0];
    const float* w_qkv  = (const float*)d_in[1];
    const float* b_qkv  = (const float*)d_in[2];
    const float* w_proj = (const float*)d_in[3];
    const float* b_proj = (const float*)d_in[4];
    float* out = (float*)d_out;

    float *qkv_p, *v_p, *ctx_p, *xc_p, *wqkvT_p, *wprojT_p;
    cudaGetSymbolAddress((void**)&qkv_p, g_qkv);
    cudaGetSymbolAddress((void**)&v_p, g_v);
    cudaGetSymbolAddress((void**)&ctx_p, g_ctx);
    cudaGetSymbolAddress((void**)&xc_p, g_xc);
    cudaGetSymbolAddress((void**)&wqkvT_p, g_wqkvT);
    cudaGetSymbolAddress((void**)&wprojT_p, g_wprojT);

    const int gemm_smem = 3 * G_STAGE;                 // 110592 B
    const int attn_smem = AT_Q + 4 * AT_T;             // 104448 B
    cudaFuncSetAttribute(gemm_tc_kernel, cudaFuncAttributeMaxDynamicSharedMemorySize, gemm_smem);
    cudaFuncSetAttribute(attn_tc_kernel, cudaFuncAttributeMaxDynamicSharedMemorySize, attn_smem);

    // 0) one-time tf32 conversions (+ weight transposes)
    conv_tf32_kernel<<<(S_LEN * D_MODEL / 4 + 255) / 256, 256>>>(
        (const float4*)x, (float4*)xc_p, S_LEN * D_MODEL / 4);
    convT_tf32_kernel<<<dim3(3 * D_MODEL / 32, D_MODEL / 32), dim3(32, 8)>>>(
        w_qkv, wqkvT_p, D_MODEL, 3 * D_MODEL);
    convT_tf32_kernel<<<dim3(D_MODEL / 32, D_MODEL / 32), dim3(32, 8)>>>(
        w_proj, wprojT_p, D_MODEL, D_MODEL);

    // 1) qkv = x @ w_qkv + b_qkv  (V columns -> transposed g_v)
    gemm_tc_kernel<<<dim3(3 * D_MODEL / 128, S_LEN / 128), 256, gemm_smem>>>(
        xc_p, wqkvT_p, b_qkv, qkv_p, S_LEN, 3 * D_MODEL, D_MODEL,
        v_p, 2 * D_MODEL, 1);

    // 2) causal flash attention -> ctx
    attn_tc_kernel<<<dim3(S_LEN / 128, NH), 256, attn_smem>>>(qkv_p, v_p, ctx_p);

    // 3) out = ctx @ w_proj + b_proj
    gemm_tc_kernel<<<dim3(D_MODEL / 128, S_LEN / 128), 256, gemm_smem>>>(
        ctx_p, wprojT_p, b_proj, out, S_LEN, D_MODEL, D_MODEL,
        nullptr, 1 << 30, 0);
}